// round 8
// baseline (speedup 1.0000x reference)
#include <cuda_runtime.h>
#include <cuda_bf16.h>
#include <cstdint>

#define N_NODES 100000
#define N_EDGES 3200000
#define BATCH   16
#define HIDDEN  64

// Lookup table for the scalar MLP f(x): 1 -> 64 GELU(erf) -> 1
#define TBL_N     16384
#define TBL_RANGE 10.0f
#define TBL_SCALE ((float)TBL_N / (2.0f * TBL_RANGE))
#define TBL_OFF   ((float)TBL_N * 0.5f)

#define TBL_BLOCKS  ((TBL_N + 1 + 255) / 256)       // 65
#define PREP_BLOCKS ((N_NODES + 255) / 256)         // 391
#define DEG_BLOCKS  ((N_EDGES + 255) / 256)         // 12500

// Scratch (device globals; zero-initialized at module load).
// INVARIANT: g_agg and g_deg are all-zero at kernel_launch entry —
// guaranteed by loader zero-init on the first call and by mlp_kernel's
// consume-and-reset on every call thereafter.
__device__ __align__(16) float g_muT[(size_t)N_NODES * BATCH];  // mu transposed [N][B]
__device__ __align__(16) float g_agg[(size_t)N_NODES * BATCH];  // accumulators  [N][B]
__device__ float g_deg[N_NODES];                                // degree counts
__device__ float g_tbl[TBL_N + 2];                              // f(x) samples

// ---------------------------------------------------------------------------
// Exact scalar MLP (erf GELU) — table build + rare out-of-range fallback.
// ---------------------------------------------------------------------------
__device__ __forceinline__ float mlp_exact(float x,
                                           const float* __restrict__ W1,
                                           const float* __restrict__ b1,
                                           const float* __restrict__ W2,
                                           const float* __restrict__ b2) {
    float acc = b2[0];
    #pragma unroll 8
    for (int h = 0; h < HIDDEN; h++) {
        const float z = fmaf(x, __ldg(W1 + h), __ldg(b1 + h));
        const float g = 0.5f * z * (1.0f + erff(z * 0.70710678118654752440f));
        acc = fmaf(g, __ldg(W2 + h), acc);
    }
    return acc;
}

__device__ __forceinline__ float lut_eval(float x,
                                          const float* __restrict__ W1,
                                          const float* __restrict__ b1,
                                          const float* __restrict__ W2,
                                          const float* __restrict__ b2) {
    const float u = fmaf(x, TBL_SCALE, TBL_OFF);
    if (u >= 0.0f && u < (float)TBL_N) {
        const int   i    = (int)u;
        const float frac = u - (float)i;
        const float t0 = __ldg(g_tbl + i);
        const float t1 = __ldg(g_tbl + i + 1);
        return fmaf(t1 - t0, frac, t0);
    }
    return mlp_exact(x, W1, b1, W2, b2);   // |x| > 10: essentially never
}

// ---------------------------------------------------------------------------
// Kernel 1 (merged, 3 block ranges):
//   [0, TBL_BLOCKS)                      build the LUT        (MUFU/FMA)
//   [TBL_BLOCKS, +PREP_BLOCKS)           transpose mu -> muT  (memory)
//   [TBL_BLOCKS+PREP_BLOCKS, +DEG_BLOCKS) degree histogram     (L2 REDs)
// The three overlap across SMs; deg REDs hide under transpose traffic.
// g_deg is zero at entry (consume-and-reset invariant).
// ---------------------------------------------------------------------------
__global__ void __launch_bounds__(256) init_kernel(const float* __restrict__ mu,
                                                   const int*   __restrict__ ei,
                                                   const float* __restrict__ W1,
                                                   const float* __restrict__ b1,
                                                   const float* __restrict__ W2,
                                                   const float* __restrict__ b2) {
    if (blockIdx.x < TBL_BLOCKS) {
        const int i = blockIdx.x * 256 + threadIdx.x;
        if (i <= TBL_N) {
            const float x = -TBL_RANGE + (2.0f * TBL_RANGE / (float)TBL_N) * (float)i;
            g_tbl[i] = mlp_exact(x, W1, b1, W2, b2);
        }
        return;
    }

    if (blockIdx.x < TBL_BLOCKS + PREP_BLOCKS) {
        const int n = (blockIdx.x - TBL_BLOCKS) * 256 + threadIdx.x;
        if (n >= N_NODES) return;

        float v[BATCH];
        #pragma unroll
        for (int b = 0; b < BATCH; b++)
            v[b] = __ldg(mu + (size_t)b * N_NODES + n);

        float4* dst = reinterpret_cast<float4*>(g_muT) + (size_t)n * 4;
        dst[0] = make_float4(v[0],  v[1],  v[2],  v[3]);
        dst[1] = make_float4(v[4],  v[5],  v[6],  v[7]);
        dst[2] = make_float4(v[8],  v[9],  v[10], v[11]);
        dst[3] = make_float4(v[12], v[13], v[14], v[15]);
        return;
    }

    // degree histogram range
    const int e = (blockIdx.x - TBL_BLOCKS - PREP_BLOCKS) * 256 + threadIdx.x;
    if (e >= N_EDGES) return;
    const int r = __ldg(ei + e);
    if ((unsigned)r < N_NODES) {
        asm volatile("red.global.add.f32 [%0], %1;"
                     :: "l"(__cvta_generic_to_global(g_deg + r)), "f"(1.0f)
                     : "memory");
    }
}

// ---------------------------------------------------------------------------
// Kernel 2: per-edge scatter, 4 lanes per edge (8 edges per warp).
// Pure gather + v4-RED now (deg moved to init).
// ---------------------------------------------------------------------------
__device__ __forceinline__ void red_add_v4(float* gptr, float4 v) {
    asm volatile("red.global.add.v4.f32 [%0], {%1, %2, %3, %4};"
                 :: "l"(__cvta_generic_to_global(gptr)),
                    "f"(v.x), "f"(v.y), "f"(v.z), "f"(v.w)
                 : "memory");
}

__global__ void __launch_bounds__(256) edge_kernel(const int* __restrict__ ei) {
    const int T = blockIdx.x * blockDim.x + threadIdx.x;
    const int e = T >> 2;        // edge id
    const int q = T & 3;         // float4 slot within the 64B row
    if (e >= N_EDGES) return;

    const int r = __ldg(ei + e);             // destination (row)
    const int c = __ldg(ei + N_EDGES + e);   // source (col)
    if ((unsigned)r >= N_NODES || (unsigned)c >= N_NODES) return;

    const float4 v = reinterpret_cast<const float4*>(g_muT)[(size_t)c * 4 + q];
    red_add_v4(g_agg + (size_t)r * BATCH + q * 4, v);
}

// ---------------------------------------------------------------------------
// Kernel 3: mean + LUT MLP, vectorized (one thread = 4 batches of one node),
// then CONSUME-AND-RESET: writes zeros back to g_agg / g_deg so the next
// invocation (graph replay) starts from a clean state without a zeroing pass.
// ---------------------------------------------------------------------------
__global__ void __launch_bounds__(512) mlp_kernel(const float* __restrict__ W1,
                                                  const float* __restrict__ b1,
                                                  const float* __restrict__ W2,
                                                  const float* __restrict__ b2,
                                                  float* __restrict__ out) {
    __shared__ float tileY[BATCH][128 + 4];

    const int t    = threadIdx.x;
    const int n0   = blockIdx.x * 128;
    const int node = t >> 2;
    const int q    = t & 3;
    const int n    = n0 + node;

    float4 y = make_float4(0.f, 0.f, 0.f, 0.f);
    if (n < N_NODES) {
        const float invd = 1.0f / fmaxf(g_deg[n], 1.0f);
        float4* aggp = reinterpret_cast<float4*>(g_agg) + (size_t)n * 4 + q;
        const float4 a = *aggp;
        *aggp = make_float4(0.f, 0.f, 0.f, 0.f);     // reset for next replay
        if (q == 0) g_deg[n] = 0.0f;                 // reset for next replay
        y.x = lut_eval(a.x * invd, W1, b1, W2, b2);
        y.y = lut_eval(a.y * invd, W1, b1, W2, b2);
        y.z = lut_eval(a.z * invd, W1, b1, W2, b2);
        y.w = lut_eval(a.w * invd, W1, b1, W2, b2);
    }
    tileY[q * 4 + 0][node] = y.x;
    tileY[q * 4 + 1][node] = y.y;
    tileY[q * 4 + 2][node] = y.z;
    tileY[q * 4 + 3][node] = y.w;
    __syncthreads();

    const int j = t & 127;
    #pragma unroll
    for (int r = 0; r < 4; r++) {
        const int b  = (t >> 7) + r * 4;
        const int nn = n0 + j;
        if (nn < N_NODES) out[(size_t)b * N_NODES + nn] = tileY[b][j];
    }
}

// ---------------------------------------------------------------------------
extern "C" void kernel_launch(void* const* d_in, const int* in_sizes, int n_in,
                              void* d_out, int out_size) {
    const float* mu = (const float*)d_in[0];
    const int*   ei = (const int*)d_in[1];     // edge_index stored as int32
    const float* W1 = (const float*)d_in[2];
    const float* b1 = (const float*)d_in[3];
    const float* W2 = (const float*)d_in[4];
    const float* b2 = (const float*)d_in[5];
    float*      out = (float*)d_out;

    init_kernel<<<TBL_BLOCKS + PREP_BLOCKS + DEG_BLOCKS, 256>>>(mu, ei, W1, b1, W2, b2);

    const long long lanes = (long long)N_EDGES * 4;
    edge_kernel<<<(int)((lanes + 255) / 256), 256>>>(ei);

    mlp_kernel<<<(N_NODES + 127) / 128, 512>>>(W1, b1, W2, b2, out);
}